// round 14
// baseline (speedup 1.0000x reference)
#include <cuda_runtime.h>
#include <cstdint>

// Type-2 NUFFT, separable:
//   stage 1 (tensor, mma.sync tf32): S[m, n=(iy*4+c)] = sum_ix E[m,ix] * X[n,ix]
//   stage 2 (FFMA, in-register):     y[b,c,m] = sum_iy ey[m,iy] (*) S[m,iy,c]
// One CTA per (frame, 64-sample tile): 512 CTAs, 512 threads (16 warps).
// X stored n-major [n][k] so gmem staging is float4-coalesced AND the
// B-fragment LDS pattern (banks 4g+q) is conflict-free.
// Dr = Er*Xr + (-Ei)*Xi ; Di = Er*Xi + Ei*Xr   (-Ei via in-register XOR)

#define NBATCH 16
#define NC 4
#define NH 64
#define NW 64
#define NM 2048

#define MT 64                    // samples per CTA
#define MTILES (NM / MT)         // 32
#define NGEMM 256                // n = iy*4 + c
#define KDIM 64                  // k = ix
#define NTHREADS 512

#define ESTRIDE 68               // floats per E row (m-major)
#define XSTRIDE 68               // floats per X row (n-major)

#define OFF_ER   0
#define OFF_EI   (OFF_ER  + MT * ESTRIDE * 4)          // 17408
#define OFF_XR   (OFF_EI  + MT * ESTRIDE * 4)          // 34816
#define OFF_XI   (OFF_XR  + NGEMM * XSTRIDE * 4)       // 104448
#define OFF_PART (OFF_XI  + NGEMM * XSTRIDE * 4)       // 174080
#define SMEM_TOTAL (OFF_PART + 4 * MT * NC * 2 * 4)    // 182272 B

static __device__ __forceinline__ uint32_t f2tf32(float f) {
    uint32_t u;
    asm("cvt.rna.tf32.f32 %0, %1;" : "=r"(u) : "f"(f));
    return u;
}

static __device__ __forceinline__ float2 twiddle(float t, int i) {
    float ph = -t * (float)(i - 32);
    ph -= 6.283185307179586f * rintf(ph * 0.15915494309189535f);
    float s, c;
    __sincosf(ph, &s, &c);
    return make_float2(c, s);
}

static __device__ __forceinline__ void mma8(float* d, const uint32_t* a, const uint32_t* b) {
    asm volatile(
        "mma.sync.aligned.m16n8k8.row.col.f32.tf32.tf32.f32 "
        "{%0,%1,%2,%3}, {%4,%5,%6,%7}, {%8,%9}, {%0,%1,%2,%3};"
        : "+f"(d[0]), "+f"(d[1]), "+f"(d[2]), "+f"(d[3])
        : "r"(a[0]), "r"(a[1]), "r"(a[2]), "r"(a[3]), "r"(b[0]), "r"(b[1]));
}

__global__ void __launch_bounds__(NTHREADS, 1)
nufft2_mma_kernel(const float* __restrict__ xre, const float* __restrict__ xim,
                  const float* __restrict__ traj, float* __restrict__ out)
{
    extern __shared__ char smc[];
    uint32_t* ER  = (uint32_t*)(smc + OFF_ER);
    uint32_t* EI  = (uint32_t*)(smc + OFF_EI);
    uint32_t* XR  = (uint32_t*)(smc + OFF_XR);
    uint32_t* XI  = (uint32_t*)(smc + OFF_XI);
    float*    PART = (float*)(smc + OFF_PART);   // [qt=4][m=64][c=4][re/im]

    const int b     = blockIdx.x >> 5;
    const int mtile = blockIdx.x & 31;
    const int m0    = mtile * MT;
    const int tid   = threadIdx.x;
    const int wid   = tid >> 5;
    const int lane  = tid & 31;

    // ---- stage E: Er/Ei[m][k], tf32; ph = -traj[...,1]*(k-32) ----
    #pragma unroll 2
    for (int e = tid; e < MT * KDIM; e += NTHREADS) {
        int ml = e >> 6, k = e & 63;
        float t1 = __ldg(traj + ((size_t)b * NM + m0 + ml) * 2 + 1);
        float2 w = twiddle(t1, k);
        int d = ml * ESTRIDE + k;
        ER[d] = f2tf32(w.x);
        EI[d] = f2tf32(w.y);
    }

    // ---- stage X: Xr/Xi[n = iy*4+c][k], float4-coalesced LDG + STS.128 ----
    const float4* xr4 = (const float4*)(xre + (size_t)b * (NC * NH * NW));
    const float4* xi4 = (const float4*)(xim + (size_t)b * (NC * NH * NW));
    #pragma unroll
    for (int f = tid; f < (NC * NH * NW) / 4; f += NTHREADS) {   // 8 iters
        int kq = f & 15;             // float4 within row (k = 4*kq..4*kq+3)
        int iy = (f >> 4) & 63;
        int c  = f >> 10;
        int n  = iy * 4 + c;
        float4 vr = __ldg(xr4 + f);
        float4 vi = __ldg(xi4 + f);
        uint4 wr = make_uint4(f2tf32(vr.x), f2tf32(vr.y), f2tf32(vr.z), f2tf32(vr.w));
        uint4 wi = make_uint4(f2tf32(vi.x), f2tf32(vi.y), f2tf32(vi.z), f2tf32(vi.w));
        *(uint4*)(XR + n * XSTRIDE + kq * 4) = wr;
        *(uint4*)(XI + n * XSTRIDE + kq * 4) = wi;
    }
    __syncthreads();

    // ---- mainloop: warp = m16-block (mb = wid&3) x 64-col n-quarter (qt = wid>>2) ----
    const int mb = wid & 3;
    const int qt = wid >> 2;
    const int g  = lane >> 2;        // groupID
    const int q  = lane & 3;         // threadID-in-group
    const int r0 = (mb * 16 + g) * ESTRIDE;
    const int r1 = r0 + 8 * ESTRIDE;

    float dr[8][4], di[8][4];
    #pragma unroll
    for (int nb = 0; nb < 8; ++nb)
        #pragma unroll
        for (int r = 0; r < 4; ++r) { dr[nb][r] = 0.f; di[nb][r] = 0.f; }

    uint32_t aR[4], aI[4];
    {
        const int k0 = q;
        aR[0] = ER[r0 + k0]; aR[1] = ER[r1 + k0];
        aR[2] = ER[r0 + k0 + 4]; aR[3] = ER[r1 + k0 + 4];
        aI[0] = EI[r0 + k0]; aI[1] = EI[r1 + k0];
        aI[2] = EI[r0 + k0 + 4]; aI[3] = EI[r1 + k0 + 4];
    }

    #pragma unroll 1
    for (int ks = 0; ks < 8; ++ks) {
        const int k0 = ks * 8 + q;
        uint32_t aN[4];
        #pragma unroll
        for (int r = 0; r < 4; ++r) aN[r] = aI[r] ^ 0x80000000u;

        uint32_t aRn[4], aIn[4];
        if (ks < 7) {
            const int kn = k0 + 8;
            aRn[0] = ER[r0 + kn]; aRn[1] = ER[r1 + kn];
            aRn[2] = ER[r0 + kn + 4]; aRn[3] = ER[r1 + kn + 4];
            aIn[0] = EI[r0 + kn]; aIn[1] = EI[r1 + kn];
            aIn[2] = EI[r0 + kn + 4]; aIn[3] = EI[r1 + kn + 4];
        }

        #pragma unroll
        for (int nb = 0; nb < 8; ++nb) {
            int nrow = (qt * 64 + nb * 8 + g) * XSTRIDE;   // n-major X
            uint32_t bR[2], bI[2];
            bR[0] = XR[nrow + k0];
            bR[1] = XR[nrow + k0 + 4];
            bI[0] = XI[nrow + k0];
            bI[1] = XI[nrow + k0 + 4];
            mma8(dr[nb], aR, bR);
            mma8(dr[nb], aN, bI);
            mma8(di[nb], aR, bI);
            mma8(di[nb], aI, bR);
        }

        #pragma unroll
        for (int r = 0; r < 4; ++r) { aR[r] = aRn[r]; aI[r] = aIn[r]; }
    }

    // ---- epilogue: ey twiddle in-register, reduce iy ----
    // d-frag: rows {g, g+8} (regs {0,1},{2,3}), cols n = qt*64+nb*8+2q+{0,1}
    //   -> iy = qt*16 + nb*2 + (q>>1), c = (q&1)*2 + {0,1}
    const int cb = (q & 1) * 2;
    #pragma unroll
    for (int rr = 0; rr < 2; ++rr) {
        int rowl = mb * 16 + g + rr * 8;
        float t0 = __ldg(traj + ((size_t)b * NM + m0 + rowl) * 2 + 0);
        float aR0 = 0.f, aI0 = 0.f, aR1 = 0.f, aI1 = 0.f;
        #pragma unroll
        for (int nb = 0; nb < 8; ++nb) {
            float2 ey = twiddle(t0, qt * 16 + nb * 2 + (q >> 1));
            float sr0 = dr[nb][rr * 2 + 0], si0 = di[nb][rr * 2 + 0];
            float sr1 = dr[nb][rr * 2 + 1], si1 = di[nb][rr * 2 + 1];
            aR0 = fmaf(ey.x, sr0, fmaf(-ey.y, si0, aR0));
            aI0 = fmaf(ey.x, si0, fmaf( ey.y, sr0, aI0));
            aR1 = fmaf(ey.x, sr1, fmaf(-ey.y, si1, aR1));
            aI1 = fmaf(ey.x, si1, fmaf( ey.y, sr1, aI1));
        }
        // partner lane (q ^ 2) holds the other iy parity, same c pair
        aR0 += __shfl_xor_sync(0xffffffffu, aR0, 2);
        aI0 += __shfl_xor_sync(0xffffffffu, aI0, 2);
        aR1 += __shfl_xor_sync(0xffffffffu, aR1, 2);
        aI1 += __shfl_xor_sync(0xffffffffu, aI1, 2);
        if (q < 2) {
            float* p = PART + ((qt * MT + rowl) * NC + cb) * 2;
            p[0] = aR0; p[1] = aI0; p[2] = aR1; p[3] = aI1;
        }
    }
    __syncthreads();

    // ---- combine 4 n-quarters, write out ----
    if (tid < MT * NC) {
        int mlocal = tid >> 2, c = tid & 3;
        float vr = 0.f, vi = 0.f;
        #pragma unroll
        for (int qq = 0; qq < 4; ++qq) {
            const float* p = PART + ((qq * MT + mlocal) * NC + c) * 2;
            vr += p[0]; vi += p[1];
        }
        *(float2*)(out + (((size_t)b * NC + c) * NM + m0 + mlocal) * 2) =
            make_float2(vr, vi);
    }
}

extern "C" void kernel_launch(void* const* d_in, const int* in_sizes, int n_in,
                              void* d_out, int out_size)
{
    const float* xre  = (const float*)d_in[0];   // [B,C,H,W] f32
    const float* xim  = (const float*)d_in[1];   // [B,C,H,W] f32
    const float* traj = (const float*)d_in[2];   // [B,M,2]   f32
    float* out        = (float*)d_out;           // [B,C,M,2] f32

    cudaFuncSetAttribute(nufft2_mma_kernel,
                         cudaFuncAttributeMaxDynamicSharedMemorySize, SMEM_TOTAL);
    nufft2_mma_kernel<<<NBATCH * MTILES, NTHREADS, SMEM_TOTAL>>>(xre, xim, traj, out);
}

// round 15
// speedup vs baseline: 1.0073x; 1.0073x over previous
#include <cuda_runtime.h>
#include <cstdint>

// Type-2 NUFFT, separable:
//   stage 1 (tensor, mma.sync tf32): S[m, n=(iy*4+c)] = sum_ix E[m,ix] * X[n,ix]
//   stage 2 (FFMA, in-register):     y[b,c,m] = sum_iy ey[m,iy] (*) S[m,iy,c]
// One CTA per (frame, 64-sample tile): 512 CTAs, 512 threads (16 warps).
// X stored n-major [n][k] so gmem staging is float4-coalesced AND the
// B-fragment LDS pattern (banks 4g+q) is conflict-free.
// Dr = Er*Xr + (-Ei)*Xi ; Di = Er*Xi + Ei*Xr   (-Ei via in-register XOR)

#define NBATCH 16
#define NC 4
#define NH 64
#define NW 64
#define NM 2048

#define MT 64                    // samples per CTA
#define MTILES (NM / MT)         // 32
#define NGEMM 256                // n = iy*4 + c
#define KDIM 64                  // k = ix
#define NTHREADS 512

#define ESTRIDE 68               // floats per E row (m-major)
#define XSTRIDE 68               // floats per X row (n-major)

#define OFF_ER   0
#define OFF_EI   (OFF_ER  + MT * ESTRIDE * 4)          // 17408
#define OFF_XR   (OFF_EI  + MT * ESTRIDE * 4)          // 34816
#define OFF_XI   (OFF_XR  + NGEMM * XSTRIDE * 4)       // 104448
#define OFF_PART (OFF_XI  + NGEMM * XSTRIDE * 4)       // 174080
#define SMEM_TOTAL (OFF_PART + 4 * MT * NC * 2 * 4)    // 182272 B

static __device__ __forceinline__ uint32_t f2tf32(float f) {
    uint32_t u;
    asm("cvt.rna.tf32.f32 %0, %1;" : "=r"(u) : "f"(f));
    return u;
}

static __device__ __forceinline__ float2 twiddle(float t, int i) {
    float ph = -t * (float)(i - 32);
    ph -= 6.283185307179586f * rintf(ph * 0.15915494309189535f);
    float s, c;
    __sincosf(ph, &s, &c);
    return make_float2(c, s);
}

static __device__ __forceinline__ void mma8(float* d, const uint32_t* a, const uint32_t* b) {
    asm volatile(
        "mma.sync.aligned.m16n8k8.row.col.f32.tf32.tf32.f32 "
        "{%0,%1,%2,%3}, {%4,%5,%6,%7}, {%8,%9}, {%0,%1,%2,%3};"
        : "+f"(d[0]), "+f"(d[1]), "+f"(d[2]), "+f"(d[3])
        : "r"(a[0]), "r"(a[1]), "r"(a[2]), "r"(a[3]), "r"(b[0]), "r"(b[1]));
}

__global__ void __launch_bounds__(NTHREADS, 1)
nufft2_mma_kernel(const float* __restrict__ xre, const float* __restrict__ xim,
                  const float* __restrict__ traj, float* __restrict__ out)
{
    extern __shared__ char smc[];
    uint32_t* ER  = (uint32_t*)(smc + OFF_ER);
    uint32_t* EI  = (uint32_t*)(smc + OFF_EI);
    uint32_t* XR  = (uint32_t*)(smc + OFF_XR);
    uint32_t* XI  = (uint32_t*)(smc + OFF_XI);
    float*    PART = (float*)(smc + OFF_PART);   // [qt=4][m=64][c=4][re/im]

    const int b     = blockIdx.x >> 5;
    const int mtile = blockIdx.x & 31;
    const int m0    = mtile * MT;
    const int tid   = threadIdx.x;
    const int wid   = tid >> 5;
    const int lane  = tid & 31;

    // ---- stage E: Er/Ei[m][k], tf32; ph = -traj[...,1]*(k-32) ----
    #pragma unroll 2
    for (int e = tid; e < MT * KDIM; e += NTHREADS) {
        int ml = e >> 6, k = e & 63;
        float t1 = __ldg(traj + ((size_t)b * NM + m0 + ml) * 2 + 1);
        float2 w = twiddle(t1, k);
        int d = ml * ESTRIDE + k;
        ER[d] = f2tf32(w.x);
        EI[d] = f2tf32(w.y);
    }

    // ---- stage X: Xr/Xi[n = iy*4+c][k], float4-coalesced LDG + STS.128 ----
    const float4* xr4 = (const float4*)(xre + (size_t)b * (NC * NH * NW));
    const float4* xi4 = (const float4*)(xim + (size_t)b * (NC * NH * NW));
    #pragma unroll
    for (int f = tid; f < (NC * NH * NW) / 4; f += NTHREADS) {   // 8 iters
        int kq = f & 15;             // float4 within row (k = 4*kq..4*kq+3)
        int iy = (f >> 4) & 63;
        int c  = f >> 10;
        int n  = iy * 4 + c;
        float4 vr = __ldg(xr4 + f);
        float4 vi = __ldg(xi4 + f);
        uint4 wr = make_uint4(f2tf32(vr.x), f2tf32(vr.y), f2tf32(vr.z), f2tf32(vr.w));
        uint4 wi = make_uint4(f2tf32(vi.x), f2tf32(vi.y), f2tf32(vi.z), f2tf32(vi.w));
        *(uint4*)(XR + n * XSTRIDE + kq * 4) = wr;
        *(uint4*)(XI + n * XSTRIDE + kq * 4) = wi;
    }
    __syncthreads();

    // ---- mainloop: warp = m16-block (mb = wid&3) x 64-col n-quarter (qt = wid>>2) ----
    const int mb = wid & 3;
    const int qt = wid >> 2;
    const int g  = lane >> 2;        // groupID
    const int q  = lane & 3;         // threadID-in-group
    const int r0 = (mb * 16 + g) * ESTRIDE;
    const int r1 = r0 + 8 * ESTRIDE;

    float dr[8][4], di[8][4];
    #pragma unroll
    for (int nb = 0; nb < 8; ++nb)
        #pragma unroll
        for (int r = 0; r < 4; ++r) { dr[nb][r] = 0.f; di[nb][r] = 0.f; }

    uint32_t aR[4], aI[4];
    {
        const int k0 = q;
        aR[0] = ER[r0 + k0]; aR[1] = ER[r1 + k0];
        aR[2] = ER[r0 + k0 + 4]; aR[3] = ER[r1 + k0 + 4];
        aI[0] = EI[r0 + k0]; aI[1] = EI[r1 + k0];
        aI[2] = EI[r0 + k0 + 4]; aI[3] = EI[r1 + k0 + 4];
    }

    #pragma unroll 1
    for (int ks = 0; ks < 8; ++ks) {
        const int k0 = ks * 8 + q;
        uint32_t aN[4];
        #pragma unroll
        for (int r = 0; r < 4; ++r) aN[r] = aI[r] ^ 0x80000000u;

        uint32_t aRn[4], aIn[4];
        if (ks < 7) {
            const int kn = k0 + 8;
            aRn[0] = ER[r0 + kn]; aRn[1] = ER[r1 + kn];
            aRn[2] = ER[r0 + kn + 4]; aRn[3] = ER[r1 + kn + 4];
            aIn[0] = EI[r0 + kn]; aIn[1] = EI[r1 + kn];
            aIn[2] = EI[r0 + kn + 4]; aIn[3] = EI[r1 + kn + 4];
        }

        #pragma unroll
        for (int nb = 0; nb < 8; ++nb) {
            int nrow = (qt * 64 + nb * 8 + g) * XSTRIDE;   // n-major X
            uint32_t bR[2], bI[2];
            bR[0] = XR[nrow + k0];
            bR[1] = XR[nrow + k0 + 4];
            bI[0] = XI[nrow + k0];
            bI[1] = XI[nrow + k0 + 4];
            mma8(dr[nb], aR, bR);
            mma8(dr[nb], aN, bI);
            mma8(di[nb], aR, bI);
            mma8(di[nb], aI, bR);
        }

        #pragma unroll
        for (int r = 0; r < 4; ++r) { aR[r] = aRn[r]; aI[r] = aIn[r]; }
    }

    // ---- epilogue: ey twiddle in-register, reduce iy ----
    // d-frag: rows {g, g+8} (regs {0,1},{2,3}), cols n = qt*64+nb*8+2q+{0,1}
    //   -> iy = qt*16 + nb*2 + (q>>1), c = (q&1)*2 + {0,1}
    const int cb = (q & 1) * 2;
    #pragma unroll
    for (int rr = 0; rr < 2; ++rr) {
        int rowl = mb * 16 + g + rr * 8;
        float t0 = __ldg(traj + ((size_t)b * NM + m0 + rowl) * 2 + 0);
        float aR0 = 0.f, aI0 = 0.f, aR1 = 0.f, aI1 = 0.f;
        #pragma unroll
        for (int nb = 0; nb < 8; ++nb) {
            float2 ey = twiddle(t0, qt * 16 + nb * 2 + (q >> 1));
            float sr0 = dr[nb][rr * 2 + 0], si0 = di[nb][rr * 2 + 0];
            float sr1 = dr[nb][rr * 2 + 1], si1 = di[nb][rr * 2 + 1];
            aR0 = fmaf(ey.x, sr0, fmaf(-ey.y, si0, aR0));
            aI0 = fmaf(ey.x, si0, fmaf( ey.y, sr0, aI0));
            aR1 = fmaf(ey.x, sr1, fmaf(-ey.y, si1, aR1));
            aI1 = fmaf(ey.x, si1, fmaf( ey.y, sr1, aI1));
        }
        // partner lane (q ^ 2) holds the other iy parity, same c pair
        aR0 += __shfl_xor_sync(0xffffffffu, aR0, 2);
        aI0 += __shfl_xor_sync(0xffffffffu, aI0, 2);
        aR1 += __shfl_xor_sync(0xffffffffu, aR1, 2);
        aI1 += __shfl_xor_sync(0xffffffffu, aI1, 2);
        if (q < 2) {
            float* p = PART + ((qt * MT + rowl) * NC + cb) * 2;
            p[0] = aR0; p[1] = aI0; p[2] = aR1; p[3] = aI1;
        }
    }
    __syncthreads();

    // ---- combine 4 n-quarters, write out ----
    if (tid < MT * NC) {
        int mlocal = tid >> 2, c = tid & 3;
        float vr = 0.f, vi = 0.f;
        #pragma unroll
        for (int qq = 0; qq < 4; ++qq) {
            const float* p = PART + ((qq * MT + mlocal) * NC + c) * 2;
            vr += p[0]; vi += p[1];
        }
        *(float2*)(out + (((size_t)b * NC + c) * NM + m0 + mlocal) * 2) =
            make_float2(vr, vi);
    }
}

extern "C" void kernel_launch(void* const* d_in, const int* in_sizes, int n_in,
                              void* d_out, int out_size)
{
    const float* xre  = (const float*)d_in[0];   // [B,C,H,W] f32
    const float* xim  = (const float*)d_in[1];   // [B,C,H,W] f32
    const float* traj = (const float*)d_in[2];   // [B,M,2]   f32
    float* out        = (float*)d_out;           // [B,C,M,2] f32

    cudaFuncSetAttribute(nufft2_mma_kernel,
                         cudaFuncAttributeMaxDynamicSharedMemorySize, SMEM_TOTAL);
    nufft2_mma_kernel<<<NBATCH * MTILES, NTHREADS, SMEM_TOTAL>>>(xre, xim, traj, out);
}

// round 16
// speedup vs baseline: 1.0849x; 1.0770x over previous
#include <cuda_runtime.h>
#include <cstdint>

// Type-2 NUFFT, separable:
//   stage 1 (tensor, mma.sync tf32): S[m, n=(iy*4+c)] = sum_ix E[m,ix] * X[n,ix]
//   stage 2 (FFMA, in-register):     y[b,c,m] = sum_iy ey[m,iy] (*) S[m,iy,c]
// n-SPLIT: one CTA per (frame, 64-sample tile, iy-half) -> 1024 CTAs, 256 thr,
// 106 KB smem -> 2 CTAs/SM so staging/epilogue of one CTA overlaps the other's
// MMAs. Halves combined with one atomicAdd per element (2 commutative adds
// from zero -> deterministic); out zeroed by a tiny prologue kernel.

#define NBATCH 16
#define NC 4
#define NH 64
#define NW 64
#define NM 2048

#define MT 64                    // samples per CTA
#define MTILES (NM / MT)         // 32
#define NLOC 128                 // n-cols per CTA (iy-half: 32 iy x 4 c)
#define KDIM 64                  // k = ix
#define NTHREADS 256

#define ESTRIDE 68               // floats per E row (m-major)
#define XSTRIDE 68               // floats per X row (n-major)

#define OFF_ER   0
#define OFF_EI   (OFF_ER  + MT * ESTRIDE * 4)          // 17408
#define OFF_XR   (OFF_EI  + MT * ESTRIDE * 4)          // 34816
#define OFF_XI   (OFF_XR  + NLOC * XSTRIDE * 4)        // 69632
#define OFF_PART (OFF_XI  + NLOC * XSTRIDE * 4)        // 104448
#define SMEM_TOTAL (OFF_PART + 2 * MT * NC * 2 * 4)    // 108544 B (x2 = 212 KB/SM)

static __device__ __forceinline__ uint32_t f2tf32(float f) {
    uint32_t u;
    asm("cvt.rna.tf32.f32 %0, %1;" : "=r"(u) : "f"(f));
    return u;
}

static __device__ __forceinline__ float2 twiddle(float t, int i) {
    float ph = -t * (float)(i - 32);
    ph -= 6.283185307179586f * rintf(ph * 0.15915494309189535f);
    float s, c;
    __sincosf(ph, &s, &c);
    return make_float2(c, s);
}

static __device__ __forceinline__ void mma8(float* d, const uint32_t* a, const uint32_t* b) {
    asm volatile(
        "mma.sync.aligned.m16n8k8.row.col.f32.tf32.tf32.f32 "
        "{%0,%1,%2,%3}, {%4,%5,%6,%7}, {%8,%9}, {%0,%1,%2,%3};"
        : "+f"(d[0]), "+f"(d[1]), "+f"(d[2]), "+f"(d[3])
        : "r"(a[0]), "r"(a[1]), "r"(a[2]), "r"(a[3]), "r"(b[0]), "r"(b[1]));
}

__global__ void zero_out_kernel(float4* out) {
    out[blockIdx.x * 256 + threadIdx.x] = make_float4(0.f, 0.f, 0.f, 0.f);
}

__global__ void __launch_bounds__(NTHREADS, 2)
nufft2_mma_kernel(const float* __restrict__ xre, const float* __restrict__ xim,
                  const float* __restrict__ traj, float* __restrict__ out)
{
    extern __shared__ char smc[];
    uint32_t* ER  = (uint32_t*)(smc + OFF_ER);
    uint32_t* EI  = (uint32_t*)(smc + OFF_EI);
    uint32_t* XR  = (uint32_t*)(smc + OFF_XR);
    uint32_t* XI  = (uint32_t*)(smc + OFF_XI);
    float*    PART = (float*)(smc + OFF_PART);   // [qt=2][m=64][c=4][re/im]

    const int bx    = blockIdx.x;
    const int half  = bx & 1;                    // iy-half: iy in [32*half, 32*half+32)
    const int mtile = (bx >> 1) & 31;
    const int b     = bx >> 6;
    const int m0    = mtile * MT;
    const int tid   = threadIdx.x;
    const int wid   = tid >> 5;
    const int lane  = tid & 31;

    // ---- stage E: Er/Ei[m][k], tf32; ph = -traj[...,1]*(k-32) ----
    #pragma unroll 2
    for (int e = tid; e < MT * KDIM; e += NTHREADS) {
        int ml = e >> 6, k = e & 63;
        float t1 = __ldg(traj + ((size_t)b * NM + m0 + ml) * 2 + 1);
        float2 w = twiddle(t1, k);
        int d = ml * ESTRIDE + k;
        ER[d] = f2tf32(w.x);
        EI[d] = f2tf32(w.y);
    }

    // ---- stage X half: Xr/Xi[n = iy_loc*4+c][k], float4-coalesced ----
    const float4* xr4 = (const float4*)(xre + (size_t)b * (NC * NH * NW));
    const float4* xi4 = (const float4*)(xim + (size_t)b * (NC * NH * NW));
    #pragma unroll
    for (int f = tid; f < NC * 32 * (NW / 4); f += NTHREADS) {   // 8 iters
        int kq     = f & 15;             // float4 within k-row
        int iy_loc = (f >> 4) & 31;
        int c      = f >> 9;
        int n      = iy_loc * 4 + c;
        int gsrc   = c * 1024 + (half * 32 + iy_loc) * 16 + kq;  // float4 index
        float4 vr = __ldg(xr4 + gsrc);
        float4 vi = __ldg(xi4 + gsrc);
        uint4 wr = make_uint4(f2tf32(vr.x), f2tf32(vr.y), f2tf32(vr.z), f2tf32(vr.w));
        uint4 wi = make_uint4(f2tf32(vi.x), f2tf32(vi.y), f2tf32(vi.z), f2tf32(vi.w));
        *(uint4*)(XR + n * XSTRIDE + kq * 4) = wr;
        *(uint4*)(XI + n * XSTRIDE + kq * 4) = wi;
    }
    __syncthreads();

    // ---- mainloop: warp = m16-block (mb = wid&3) x 64-col n-half (qt = wid>>2) ----
    const int mb = wid & 3;
    const int qt = wid >> 2;         // 0..1
    const int g  = lane >> 2;        // groupID
    const int q  = lane & 3;         // threadID-in-group
    const int r0 = (mb * 16 + g) * ESTRIDE;
    const int r1 = r0 + 8 * ESTRIDE;

    float dr[8][4], di[8][4];
    #pragma unroll
    for (int nb = 0; nb < 8; ++nb)
        #pragma unroll
        for (int r = 0; r < 4; ++r) { dr[nb][r] = 0.f; di[nb][r] = 0.f; }

    uint32_t aR[4], aI[4];
    {
        const int k0 = q;
        aR[0] = ER[r0 + k0]; aR[1] = ER[r1 + k0];
        aR[2] = ER[r0 + k0 + 4]; aR[3] = ER[r1 + k0 + 4];
        aI[0] = EI[r0 + k0]; aI[1] = EI[r1 + k0];
        aI[2] = EI[r0 + k0 + 4]; aI[3] = EI[r1 + k0 + 4];
    }

    #pragma unroll 1
    for (int ks = 0; ks < 8; ++ks) {
        const int k0 = ks * 8 + q;
        uint32_t aN[4];
        #pragma unroll
        for (int r = 0; r < 4; ++r) aN[r] = aI[r] ^ 0x80000000u;

        uint32_t aRn[4], aIn[4];
        if (ks < 7) {
            const int kn = k0 + 8;
            aRn[0] = ER[r0 + kn]; aRn[1] = ER[r1 + kn];
            aRn[2] = ER[r0 + kn + 4]; aRn[3] = ER[r1 + kn + 4];
            aIn[0] = EI[r0 + kn]; aIn[1] = EI[r1 + kn];
            aIn[2] = EI[r0 + kn + 4]; aIn[3] = EI[r1 + kn + 4];
        }

        #pragma unroll
        for (int nb = 0; nb < 8; ++nb) {
            int nrow = (qt * 64 + nb * 8 + g) * XSTRIDE;   // n-major X
            uint32_t bR[2], bI[2];
            bR[0] = XR[nrow + k0];
            bR[1] = XR[nrow + k0 + 4];
            bI[0] = XI[nrow + k0];
            bI[1] = XI[nrow + k0 + 4];
            mma8(dr[nb], aR, bR);
            mma8(dr[nb], aN, bI);
            mma8(di[nb], aR, bI);
            mma8(di[nb], aI, bR);
        }

        #pragma unroll
        for (int r = 0; r < 4; ++r) { aR[r] = aRn[r]; aI[r] = aIn[r]; }
    }

    // ---- epilogue: ey twiddle in-register, reduce iy ----
    // d-frag: rows {g, g+8} (regs {0,1},{2,3}), local col n = qt*64+nb*8+2q+{0,1}
    //   -> iy = half*32 + qt*16 + nb*2 + (q>>1), c = (q&1)*2 + {0,1}
    const int cb = (q & 1) * 2;
    #pragma unroll
    for (int rr = 0; rr < 2; ++rr) {
        int rowl = mb * 16 + g + rr * 8;
        float t0 = __ldg(traj + ((size_t)b * NM + m0 + rowl) * 2 + 0);
        float aR0 = 0.f, aI0 = 0.f, aR1 = 0.f, aI1 = 0.f;
        #pragma unroll
        for (int nb = 0; nb < 8; ++nb) {
            float2 ey = twiddle(t0, half * 32 + qt * 16 + nb * 2 + (q >> 1));
            float sr0 = dr[nb][rr * 2 + 0], si0 = di[nb][rr * 2 + 0];
            float sr1 = dr[nb][rr * 2 + 1], si1 = di[nb][rr * 2 + 1];
            aR0 = fmaf(ey.x, sr0, fmaf(-ey.y, si0, aR0));
            aI0 = fmaf(ey.x, si0, fmaf( ey.y, sr0, aI0));
            aR1 = fmaf(ey.x, sr1, fmaf(-ey.y, si1, aR1));
            aI1 = fmaf(ey.x, si1, fmaf( ey.y, sr1, aI1));
        }
        // partner lane (q ^ 2) holds the other iy parity, same c pair
        aR0 += __shfl_xor_sync(0xffffffffu, aR0, 2);
        aI0 += __shfl_xor_sync(0xffffffffu, aI0, 2);
        aR1 += __shfl_xor_sync(0xffffffffu, aR1, 2);
        aI1 += __shfl_xor_sync(0xffffffffu, aI1, 2);
        if (q < 2) {
            float* p = PART + ((qt * MT + rowl) * NC + cb) * 2;
            p[0] = aR0; p[1] = aI0; p[2] = aR1; p[3] = aI1;
        }
    }
    __syncthreads();

    // ---- combine the 2 qt halves, one atomicAdd per element ----
    {
        int mlocal = tid >> 2, c = tid & 3;          // 256 threads = 64 m x 4 c
        float vr = PART[((0 * MT + mlocal) * NC + c) * 2 + 0]
                 + PART[((1 * MT + mlocal) * NC + c) * 2 + 0];
        float vi = PART[((0 * MT + mlocal) * NC + c) * 2 + 1]
                 + PART[((1 * MT + mlocal) * NC + c) * 2 + 1];
        float* o = out + (((size_t)b * NC + c) * NM + m0 + mlocal) * 2;
        atomicAdd(o + 0, vr);
        atomicAdd(o + 1, vi);
    }
}

extern "C" void kernel_launch(void* const* d_in, const int* in_sizes, int n_in,
                              void* d_out, int out_size)
{
    const float* xre  = (const float*)d_in[0];   // [B,C,H,W] f32
    const float* xim  = (const float*)d_in[1];   // [B,C,H,W] f32
    const float* traj = (const float*)d_in[2];   // [B,M,2]   f32
    float* out        = (float*)d_out;           // [B,C,M,2] f32

    // zero out: 16*4*2048*2 floats = 65536 float4
    zero_out_kernel<<<256, 256>>>((float4*)out);

    cudaFuncSetAttribute(nufft2_mma_kernel,
                         cudaFuncAttributeMaxDynamicSharedMemorySize, SMEM_TOTAL);
    nufft2_mma_kernel<<<NBATCH * MTILES * 2, NTHREADS, SMEM_TOTAL>>>(xre, xim, traj, out);
}